// round 4
// baseline (speedup 1.0000x reference)
#include <cuda_runtime.h>

#define L4 4
#define B8 8
#define PP 1369
#define DD 1024
#define NP 7            /* B-1 */
#define NPAIR 28
#define PHW 37
#define HH 518
#define NGROUP 32       /* L*B */
#define NELEM (PP*DD)
#define TOTAL (NGROUP*NELEM)
#define NTILE 11        /* ceil(1369/128) */
#define LN_EPS 1e-5f

#define PIXEL_OFF 8
#define IDX_OFF (8 + B8*HH*HH)      /* 8 + 2,146,592 = 2,146,600 */

/* ---------------- scratch (static device globals: allocation-free) -------- */
__device__ float g_fn[TOTAL];                       /* layernormed features  */
__device__ float g_X[TOTAL];                        /* smoothed+normalized   */
__device__ float g_part[NGROUP * 8 * 2];
__device__ float g_stats[NGROUP * 2];               /* mean, inv_std         */
__device__ unsigned long long g_best[L4 * B8 * PP * NP];
__device__ float g_scorep[12 * B8 * PP];            /* per (r,l) scores      */
__device__ float g_scores[B8 * PP];
__device__ float g_simg[B8];

/* ---------------- helpers ------------------------------------------------- */
__device__ __forceinline__ unsigned long long packmax(float v, int q) {
    unsigned int b = __float_as_uint(v);
    b = (b & 0x80000000u) ? ~b : (b | 0x80000000u);   /* monotonic float key */
    /* low word: inverted index so ties pick the SMALLEST q (argmin-first)   */
    return ((unsigned long long)b << 32) |
           (unsigned long long)(0x7FFFFFFFu - (unsigned int)q);
}

/* ---------------- LayerNorm ---------------------------------------------- */
__global__ void ln_stats1(const float* __restrict__ x) {
    int g = blockIdx.x, s = blockIdx.y;
    const int chunk = NELEM / 8;
    size_t base = (size_t)g * NELEM + (size_t)s * chunk;
    float sum = 0.f, sq = 0.f;
    for (int i = threadIdx.x; i < chunk; i += blockDim.x) {
        float v = x[base + i];
        sum += v; sq += v * v;
    }
    __shared__ float r1[256], r2[256];
    r1[threadIdx.x] = sum; r2[threadIdx.x] = sq;
    __syncthreads();
    for (int o = 128; o > 0; o >>= 1) {
        if (threadIdx.x < o) {
            r1[threadIdx.x] += r1[threadIdx.x + o];
            r2[threadIdx.x] += r2[threadIdx.x + o];
        }
        __syncthreads();
    }
    if (threadIdx.x == 0) {
        g_part[(g * 8 + s) * 2 + 0] = r1[0];
        g_part[(g * 8 + s) * 2 + 1] = r2[0];
    }
}

__global__ void ln_stats2() {
    int t = threadIdx.x;
    if (t < NGROUP) {
        float sum = 0.f, sq = 0.f;
        for (int s = 0; s < 8; s++) {
            sum += g_part[(t * 8 + s) * 2 + 0];
            sq  += g_part[(t * 8 + s) * 2 + 1];
        }
        float mean = sum / (float)NELEM;
        float var  = sq / (float)NELEM - mean * mean;
        g_stats[t * 2 + 0] = mean;
        g_stats[t * 2 + 1] = 1.0f / sqrtf(var + LN_EPS);
    }
}

__global__ void ln_apply(const float* __restrict__ x) {
    const int n4 = TOTAL / 4;
    const int g4 = NELEM / 4;
    for (int i = blockIdx.x * blockDim.x + threadIdx.x; i < n4;
         i += gridDim.x * blockDim.x) {
        int g = i / g4;
        float mean = g_stats[g * 2 + 0];
        float inv  = g_stats[g * 2 + 1];
        float4 v = ((const float4*)x)[i];
        v.x = (v.x - mean) * inv;
        v.y = (v.y - mean) * inv;
        v.z = (v.z - mean) * inv;
        v.w = (v.w - mean) * inv;
        ((float4*)g_fn)[i] = v;
    }
}

/* ---------------- box smooth + row L2 normalize --------------------------- */
__global__ void smooth_norm(int r) {
    int p  = blockIdx.x;
    int lb = blockIdx.y;
    int py = p / PHW, px = p % PHW;
    int pad = r >> 1;
    int t = threadIdx.x;                     /* 256 threads, 4 floats each */
    const float4* src = (const float4*)g_fn + (size_t)lb * (NELEM / 4);

    float4 acc = make_float4(0.f, 0.f, 0.f, 0.f);
    for (int dy = -pad; dy <= pad; dy++) {
        int ny = py + dy;
        if ((unsigned)ny >= PHW) continue;
        for (int dx = -pad; dx <= pad; dx++) {
            int nx = px + dx;
            if ((unsigned)nx >= PHW) continue;
            float4 v = src[(ny * PHW + nx) * (DD / 4) + t];
            acc.x += v.x; acc.y += v.y; acc.z += v.z; acc.w += v.w;
        }
    }
    float inv_rr = 1.0f / (float)(r * r);
    acc.x *= inv_rr; acc.y *= inv_rr; acc.z *= inv_rr; acc.w *= inv_rr;

    float ss = acc.x * acc.x + acc.y * acc.y + acc.z * acc.z + acc.w * acc.w;
    __shared__ float red[256];
    red[t] = ss;
    __syncthreads();
    for (int o = 128; o > 0; o >>= 1) {
        if (t < o) red[t] += red[t + o];
        __syncthreads();
    }
    __shared__ float s_inv;
    if (t == 0) s_inv = 1.0f / sqrtf(red[0]);
    __syncthreads();
    float iv = s_inv;
    acc.x *= iv; acc.y *= iv; acc.z *= iv; acc.w *= iv;
    ((float4*)g_X)[(size_t)lb * (NELEM / 4) + p * (DD / 4) + t] = acc;
}

/* ---------------- reset best buffer --------------------------------------- */
__global__ void reset_best() {
    const int n = L4 * B8 * PP * NP;
    for (int i = blockIdx.x * blockDim.x + threadIdx.x; i < n;
         i += gridDim.x * blockDim.x)
        g_best[i] = 0ULL;
}

/* ---------------- fused Gram GEMM + row/col argmax ------------------------ */
#define BM 128
#define BN 128
#define BK 16
#define PADM (BM + 4)

__global__ __launch_bounds__(256, 2) void gemm_max() {
    __shared__ float As[BK][PADM];
    __shared__ float Bs[BK][PADM];
    __shared__ unsigned long long s_row[BM];
    __shared__ unsigned long long s_col[BN];

    int l = blockIdx.y;
    int t = blockIdx.x;
    int tileId = t % (NTILE * NTILE);
    int pairId = t / (NTILE * NTILE);
    int tp = tileId / NTILE, tq = tileId % NTILE;

    int ii = 0, rem = pairId;
    while (rem >= 7 - ii) { rem -= 7 - ii; ii++; }
    int jj = ii + 1 + rem;                  /* pair (ii < jj) */

    const float* A  = g_X + (size_t)(l * B8 + ii) * PP * DD;
    const float* Bp = g_X + (size_t)(l * B8 + jj) * PP * DD;
    int pBase = tp * BM, qBase = tq * BN;

    int tid = threadIdx.x;
    int tx = tid & 15, ty = tid >> 4;

    if (tid < BM) s_row[tid] = 0ULL;
    else          s_col[tid - BM] = 0ULL;

    float acc[8][8];
#pragma unroll
    for (int i = 0; i < 8; i++)
#pragma unroll
        for (int j = 0; j < 8; j++) acc[i][j] = 0.f;

    const int v0 = tid, v1 = tid + 256;     /* float4 slots: 512 per tile   */
    const int r0 = v0 >> 2, kc0 = v0 & 3;
    const int r1 = v1 >> 2, kc1 = v1 & 3;

    for (int k0 = 0; k0 < DD; k0 += BK) {
        float4 a0 = (pBase + r0 < PP)
            ? *(const float4*)(A + (size_t)(pBase + r0) * DD + k0 + kc0 * 4)
            : make_float4(0.f, 0.f, 0.f, 0.f);
        float4 a1 = (pBase + r1 < PP)
            ? *(const float4*)(A + (size_t)(pBase + r1) * DD + k0 + kc1 * 4)
            : make_float4(0.f, 0.f, 0.f, 0.f);
        float4 b0 = (qBase + r0 < PP)
            ? *(const float4*)(Bp + (size_t)(qBase + r0) * DD + k0 + kc0 * 4)
            : make_float4(0.f, 0.f, 0.f, 0.f);
        float4 b1 = (qBase + r1 < PP)
            ? *(const float4*)(Bp + (size_t)(qBase + r1) * DD + k0 + kc1 * 4)
            : make_float4(0.f, 0.f, 0.f, 0.f);

        As[kc0 * 4 + 0][r0] = a0.x; As[kc0 * 4 + 1][r0] = a0.y;
        As[kc0 * 4 + 2][r0] = a0.z; As[kc0 * 4 + 3][r0] = a0.w;
        As[kc1 * 4 + 0][r1] = a1.x; As[kc1 * 4 + 1][r1] = a1.y;
        As[kc1 * 4 + 2][r1] = a1.z; As[kc1 * 4 + 3][r1] = a1.w;
        Bs[kc0 * 4 + 0][r0] = b0.x; Bs[kc0 * 4 + 1][r0] = b0.y;
        Bs[kc0 * 4 + 2][r0] = b0.z; Bs[kc0 * 4 + 3][r0] = b0.w;
        Bs[kc1 * 4 + 0][r1] = b1.x; Bs[kc1 * 4 + 1][r1] = b1.y;
        Bs[kc1 * 4 + 2][r1] = b1.z; Bs[kc1 * 4 + 3][r1] = b1.w;
        __syncthreads();

#pragma unroll
        for (int kk = 0; kk < BK; kk++) {
            float a[8], b[8];
#pragma unroll
            for (int i = 0; i < 8; i++) a[i] = As[kk][ty * 8 + i];
#pragma unroll
            for (int j = 0; j < 8; j++) b[j] = Bs[kk][tx * 8 + j];
#pragma unroll
            for (int i = 0; i < 8; i++)
#pragma unroll
                for (int j = 0; j < 8; j++) acc[i][j] += a[i] * b[j];
        }
        __syncthreads();
    }

    /* row maxes (query ii over refs in image jj) */
#pragma unroll
    for (int i = 0; i < 8; i++) {
        unsigned long long pk = 0ULL;
#pragma unroll
        for (int j = 0; j < 8; j++) {
            int q = qBase + tx * 8 + j;
            if (q < PP) {
                unsigned long long e = packmax(acc[i][j], q);
                if (e > pk) pk = e;
            }
        }
        if (pk) atomicMax(&s_row[ty * 8 + i], pk);
    }
    /* col maxes (query jj over refs in image ii) */
#pragma unroll
    for (int j = 0; j < 8; j++) {
        unsigned long long pk = 0ULL;
#pragma unroll
        for (int i = 0; i < 8; i++) {
            int pg = pBase + ty * 8 + i;
            if (pg < PP) {
                unsigned long long e = packmax(acc[i][j], pg);
                if (e > pk) pk = e;
            }
        }
        if (pk) atomicMax(&s_col[tx * 8 + j], pk);
    }
    __syncthreads();

    int slot_i = jj - 1;   /* position of jj in others(ii), jj > ii */
    int slot_j = ii;       /* position of ii in others(jj), ii < jj */
    if (tid < BM) {
        int pg = pBase + tid;
        if (pg < PP && s_row[tid])
            atomicMax(&g_best[((size_t)(l * B8 + ii) * PP + pg) * NP + slot_i],
                      s_row[tid]);
    } else {
        int q = qBase + (tid - BM);
        if (q < PP && s_col[tid - BM])
            atomicMax(&g_best[((size_t)(l * B8 + jj) * PP + q) * NP + slot_j],
                      s_col[tid - BM]);
    }
}

/* ---------------- drain: dist, argmin output, per-(r,l) score ------------- */
__global__ void drain(float* __restrict__ out, int rIdx) {
    int idx = blockIdx.x * blockDim.x + threadIdx.x;
    if (idx >= L4 * B8 * PP) return;
    int p  = idx % PP;
    int lb = idx / PP;
    int b = lb % B8, l = lb / B8;

    size_t base = (size_t)idx * NP;
    float m0 = 3e38f, m1 = 3e38f;
#pragma unroll
    for (int s = 0; s < NP; s++) {
        unsigned long long pk = g_best[base + s];
        unsigned int hi = (unsigned int)(pk >> 32);
        unsigned int bits = (hi & 0x80000000u) ? (hi ^ 0x80000000u) : ~hi;
        float dot = __uint_as_float(bits);
        float dist = sqrtf(fmaxf(0.f, 2.f - 2.f * dot));
        int q = (int)(0x7FFFFFFFu - (unsigned int)(pk & 0xFFFFFFFFu));
        /* min_indices layout: (B, L, R, B-1, P) */
        out[IDX_OFF +
            ((((size_t)b * L4 + l) * 3 + rIdx) * NP + s) * PP + p] = (float)q;
        if (dist < m0) { m1 = m0; m0 = dist; }
        else if (dist < m1) { m1 = dist; }
    }
    g_scorep[(size_t)(rIdx * L4 + l) * (B8 * PP) + b * PP + p] =
        0.5f * (m0 + m1);
}

/* ---------------- finalize scores ----------------------------------------- */
__global__ void finalize_scores() {
    int idx = blockIdx.x * blockDim.x + threadIdx.x;
    if (idx >= B8 * PP) return;
    float s = 0.f;
    for (int k = 0; k < 12; k++) s += g_scorep[(size_t)k * (B8 * PP) + idx];
    g_scores[idx] = s * (1.0f / 12.0f);
}

__global__ void simg_max() {
    int b = blockIdx.x;
    __shared__ float red[128];
    float m = -3e38f;
    for (int p = threadIdx.x; p < PP; p += 128)
        m = fmaxf(m, g_scores[b * PP + p]);
    red[threadIdx.x] = m;
    __syncthreads();
    for (int o = 64; o > 0; o >>= 1) {
        if (threadIdx.x < o)
            red[threadIdx.x] = fmaxf(red[threadIdx.x], red[threadIdx.x + o]);
        __syncthreads();
    }
    if (threadIdx.x == 0) g_simg[b] = red[0];
}

/* ---------------- bilinear upsample 37x37 -> 518x518 ---------------------- */
__global__ void pixel_kernel(float* __restrict__ out) {
    const int total = B8 * HH * HH;
    int idx = blockIdx.x * blockDim.x + threadIdx.x;
    if (idx >= total) return;
    int w = idx % HH;
    int rest = idx / HH;
    int h = rest % HH;
    int b = rest / HH;

    const float scale = (float)(36.0 / 517.0);
    float cy = (float)h * scale;
    int y0 = (int)cy; if (y0 > 36) y0 = 36;
    int y1 = y0 + 1 < 37 ? y0 + 1 : 36;
    float wy = cy - (float)y0;
    float cx = (float)w * scale;
    int x0 = (int)cx; if (x0 > 36) x0 = 36;
    int x1 = x0 + 1 < 37 ? x0 + 1 : 36;
    float wx = cx - (float)x0;

    const float* S = g_scores + b * PP;
    float v00 = S[y0 * PHW + x0], v01 = S[y0 * PHW + x1];
    float v10 = S[y1 * PHW + x0], v11 = S[y1 * PHW + x1];
    float top = (1.f - wx) * v00 + wx * v01;
    float bot = (1.f - wx) * v10 + wx * v11;
    out[PIXEL_OFF + idx] = (1.f - wy) * top + wy * bot;
}

/* ---------------- RsCIN final scores -------------------------------------- */
__global__ void rscin_kernel(const float* __restrict__ cls,
                             float* __restrict__ out) {
    __shared__ float sd[8][8];
    __shared__ float si[8];
    int t = threadIdx.x;               /* 64 threads */
    int i = t >> 3, j = t & 7;
    float d = 0.f;
    for (int k = 0; k < 768; k++) d += cls[i * 768 + k] * cls[j * 768 + k];
    sd[i][j] = d;
    if (t < 8) si[t] = g_simg[t];
    __syncthreads();

    if (t < 8) {
        int b = t;
        float sim[8];
        float dbb = sd[b][b];
#pragma unroll
        for (int jj = 0; jj < 8; jj++)
            sim[jj] = sd[b][jj] / sqrtf(dbb * sd[jj][jj]);

        bool used[8] = {false, false, false, false, false, false, false, false};
        float wsum = 0.f, acc = 0.f, fin = 0.f;
        for (int kk = 0; kk < 3; kk++) {
            int bi = 0; float bv = -3e38f;
            for (int j2 = 0; j2 < 8; j2++)
                if (!used[j2] && sim[j2] > bv) { bv = sim[j2]; bi = j2; }
            used[bi] = true;
            wsum += bv;
            acc += bv * si[bi];
            fin += acc / wsum;          /* result for k = kk+1 */
        }
        out[b] = fin * (1.0f / 3.0f);
    }
}

/* ---------------- launch -------------------------------------------------- */
extern "C" void kernel_launch(void* const* d_in, const int* in_sizes, int n_in,
                              void* d_out, int out_size) {
    const float* feat = (const float*)d_in[0];
    const float* cls  = (const float*)d_in[1];
    float* out = (float*)d_out;

    ln_stats1<<<dim3(NGROUP, 8), 256>>>(feat);
    ln_stats2<<<1, 32>>>();
    ln_apply<<<4096, 256>>>(feat);

    const int rlist[3] = {1, 3, 5};
    for (int ri = 0; ri < 3; ri++) {
        smooth_norm<<<dim3(PP, NGROUP), 256>>>(rlist[ri]);
        reset_best<<<256, 256>>>();
        gemm_max<<<dim3(NTILE * NTILE * NPAIR, L4), 256>>>();
        drain<<<(L4 * B8 * PP + 255) / 256, 256>>>(out, ri);
    }

    finalize_scores<<<(B8 * PP + 255) / 256, 256>>>();
    simg_max<<<B8, 128>>>();
    pixel_kernel<<<(B8 * HH * HH + 255) / 256, 256>>>(out);
    rscin_kernel<<<1, 64>>>(cls, out);
}

// round 12
// speedup vs baseline: 1.0076x; 1.0076x over previous
#include <cuda_runtime.h>
#include <cuda_fp16.h>

#define L4 4
#define B8 8
#define PP 1369
#define DD 1024
#define NP 7            /* B-1 */
#define NPAIR 28
#define PHW 37
#define HH 518
#define NGROUP 32       /* L*B */
#define NELEM (PP*DD)
#define TOTAL (NGROUP*NELEM)
#define NTILE 11        /* ceil(1369/128) */
#define LN_EPS 1e-5f
#define LSCALE 2048.0f
#define INV_LSCALE (1.0f/2048.0f)
#define DELTA 4e-5f     /* near-tie window on key scale (2*dot) */

#define PIXEL_OFF 8
#define IDX_OFF (8 + B8*HH*HH)

/* ---------------- scratch (static device globals: allocation-free) -------- */
__device__ float g_fn[TOTAL];                       /* layernormed features  */
__device__ __half g_Xh[TOTAL];                      /* split hi (fp16)       */
__device__ __half g_Xl[TOTAL];                      /* split lo*2048 (fp16)  */
__device__ float g_D [(size_t)L4 * NPAIR * PP * PP];   /* row keys [p][q]    */
__device__ float g_DT[(size_t)L4 * NPAIR * PP * PP];   /* col keys [q][p]    */
__device__ double g_ssd[NGROUP * PP];               /* fp64 sumsq quantized  */
__device__ float  g_ssf[NGROUP * PP];
__device__ float g_part[NGROUP * 8 * 2];
__device__ float g_stats[NGROUP * 2];
__device__ unsigned long long g_best[L4 * B8 * PP * NP];
__device__ float g_scorep[12 * B8 * PP];
__device__ float g_scores[B8 * PP];
__device__ float g_simg[B8];

/* ---------------- helpers ------------------------------------------------- */
__device__ __forceinline__ unsigned long long packmax(float v, int q) {
    unsigned int b = __float_as_uint(v);
    b = (b & 0x80000000u) ? ~b : (b | 0x80000000u);   /* monotonic float key */
    return ((unsigned long long)b << 32) |
           (unsigned long long)(0x7FFFFFFFu - (unsigned int)q);
}

__device__ __forceinline__ float unpackval(unsigned long long pk) {
    unsigned int hi = (unsigned int)(pk >> 32);
    unsigned int bits = (hi & 0x80000000u) ? (hi ^ 0x80000000u) : ~hi;
    return __uint_as_float(bits);
}

/* ---------------- LayerNorm ---------------------------------------------- */
__global__ void ln_stats1(const float* __restrict__ x) {
    int g = blockIdx.x, s = blockIdx.y;
    const int chunk = NELEM / 8;
    size_t base = (size_t)g * NELEM + (size_t)s * chunk;
    float sum = 0.f, sq = 0.f;
    for (int i = threadIdx.x; i < chunk; i += blockDim.x) {
        float v = x[base + i];
        sum += v; sq += v * v;
    }
    __shared__ float r1[256], r2[256];
    r1[threadIdx.x] = sum; r2[threadIdx.x] = sq;
    __syncthreads();
    for (int o = 128; o > 0; o >>= 1) {
        if (threadIdx.x < o) {
            r1[threadIdx.x] += r1[threadIdx.x + o];
            r2[threadIdx.x] += r2[threadIdx.x + o];
        }
        __syncthreads();
    }
    if (threadIdx.x == 0) {
        g_part[(g * 8 + s) * 2 + 0] = r1[0];
        g_part[(g * 8 + s) * 2 + 1] = r2[0];
    }
}

__global__ void ln_stats2() {
    int t = threadIdx.x;
    if (t < NGROUP) {
        float sum = 0.f, sq = 0.f;
        for (int s = 0; s < 8; s++) {
            sum += g_part[(t * 8 + s) * 2 + 0];
            sq  += g_part[(t * 8 + s) * 2 + 1];
        }
        float mean = sum / (float)NELEM;
        float var  = sq / (float)NELEM - mean * mean;
        g_stats[t * 2 + 0] = mean;
        g_stats[t * 2 + 1] = 1.0f / sqrtf(var + LN_EPS);
    }
}

__global__ void ln_apply(const float* __restrict__ x) {
    const int n4 = TOTAL / 4;
    const int g4 = NELEM / 4;
    for (int i = blockIdx.x * blockDim.x + threadIdx.x; i < n4;
         i += gridDim.x * blockDim.x) {
        int g = i / g4;
        float mean = g_stats[g * 2 + 0];
        float inv  = g_stats[g * 2 + 1];
        float4 v = ((const float4*)x)[i];
        v.x = (v.x - mean) * inv;
        v.y = (v.y - mean) * inv;
        v.z = (v.z - mean) * inv;
        v.w = (v.w - mean) * inv;
        ((float4*)g_fn)[i] = v;
    }
}

/* --- box smooth + row L2 normalize + scaled fp16 split -------------------- */
__global__ void smooth_norm(int r) {
    int p  = blockIdx.x;
    int lb = blockIdx.y;
    int py = p / PHW, px = p % PHW;
    int pad = r >> 1;
    int t = threadIdx.x;                     /* 256 threads, 4 floats each */
    const float4* src = (const float4*)g_fn + (size_t)lb * (NELEM / 4);

    float4 acc = make_float4(0.f, 0.f, 0.f, 0.f);
    for (int dy = -pad; dy <= pad; dy++) {
        int ny = py + dy;
        if ((unsigned)ny >= PHW) continue;
        for (int dx = -pad; dx <= pad; dx++) {
            int nx = px + dx;
            if ((unsigned)nx >= PHW) continue;
            float4 v = src[(ny * PHW + nx) * (DD / 4) + t];
            acc.x += v.x; acc.y += v.y; acc.z += v.z; acc.w += v.w;
        }
    }
    float inv_rr = 1.0f / (float)(r * r);
    acc.x *= inv_rr; acc.y *= inv_rr; acc.z *= inv_rr; acc.w *= inv_rr;

    float ss = acc.x * acc.x + acc.y * acc.y + acc.z * acc.z + acc.w * acc.w;
    __shared__ float red[256];
    red[t] = ss;
    __syncthreads();
    for (int o = 128; o > 0; o >>= 1) {
        if (t < o) red[t] += red[t + o];
        __syncthreads();
    }
    __shared__ float s_inv;
    if (t == 0) s_inv = 1.0f / sqrtf(red[0]);
    __syncthreads();
    float iv = s_inv;
    float v[4] = {acc.x * iv, acc.y * iv, acc.z * iv, acc.w * iv};

    ushort4 hpack, lpack;
    {
        unsigned short hp[4], lp[4];
#pragma unroll
        for (int e = 0; e < 4; e++) {
            __half h = __float2half_rn(v[e]);
            float hf = __half2float(h);
            __half lq = __float2half_rn((v[e] - hf) * LSCALE);
            hp[e] = __half_as_ushort(h);
            lp[e] = __half_as_ushort(lq);
        }
        hpack = make_ushort4(hp[0], hp[1], hp[2], hp[3]);
        lpack = make_ushort4(lp[0], lp[1], lp[2], lp[3]);
    }
    size_t e4 = ((size_t)lb * NELEM + (size_t)p * DD) / 4 + t;
    ((ushort4*)g_Xh)[e4] = hpack;
    ((ushort4*)g_Xl)[e4] = lpack;
}

/* --------- fp64 sumsq of quantized patch vectors (deterministic) ---------- */
__global__ void sumsq_d() {
    int pidx = blockIdx.x;                  /* lb*PP + p */
    const __half* Xh = g_Xh + (size_t)pidx * DD;
    const __half* Xl = g_Xl + (size_t)pidx * DD;
    int t = threadIdx.x;                    /* 128 threads */
    double s = 0.0;
    for (int e = t; e < DD; e += 128) {
        double x = (double)__half2float(Xh[e])
                 + (double)__half2float(Xl[e]) * (double)INV_LSCALE;
        s = fma(x, x, s);
    }
    __shared__ double red[128];
    red[t] = s;
    __syncthreads();
    for (int o = 64; o > 0; o >>= 1) {
        if (t < o) red[t] += red[t + o];
        __syncthreads();
    }
    if (t == 0) { g_ssd[pidx] = red[0]; g_ssf[pidx] = (float)red[0]; }
}

/* -------- fused Gram GEMM (scaled fp16 split) -> key matrices D, DT ------- */
#define BM 128
#define BN 128
#define BK 32
#define SPAD (BK + 8)           /* 40 halves stride: conflict-free */

__device__ __forceinline__ void mma_f16(float c[4], unsigned a0, unsigned a1,
                                        unsigned a2, unsigned a3,
                                        unsigned b0, unsigned b1) {
    asm volatile(
        "mma.sync.aligned.m16n8k16.row.col.f32.f16.f16.f32 "
        "{%0,%1,%2,%3}, {%4,%5,%6,%7}, {%8,%9}, {%0,%1,%2,%3};\n"
        : "+f"(c[0]), "+f"(c[1]), "+f"(c[2]), "+f"(c[3])
        : "r"(a0), "r"(a1), "r"(a2), "r"(a3), "r"(b0), "r"(b1));
}

__global__ __launch_bounds__(256, 1) void gemm_mma() {
    __shared__ __align__(16) __half Ah[BM][SPAD];
    __shared__ __align__(16) __half Al[BM][SPAD];
    __shared__ __align__(16) __half Bh[BN][SPAD];
    __shared__ __align__(16) __half Bl[BN][SPAD];
    __shared__ float s_ssA[BM];          /* q2 of A-rows  */
    __shared__ float s_ssB[BN];          /* r2 of B-rows  */

    int l = blockIdx.y;
    int t = blockIdx.x;
    int tileId = t % (NTILE * NTILE);
    int pairId = t / (NTILE * NTILE);
    int tp = tileId / NTILE, tq = tileId % NTILE;

    int ii = 0, rem = pairId;
    while (rem >= 7 - ii) { rem -= 7 - ii; ii++; }
    int jj = ii + 1 + rem;                  /* pair (ii < jj) */

    const __half* A_h = g_Xh + (size_t)(l * B8 + ii) * NELEM;
    const __half* A_l = g_Xl + (size_t)(l * B8 + ii) * NELEM;
    const __half* B_h = g_Xh + (size_t)(l * B8 + jj) * NELEM;
    const __half* B_l = g_Xl + (size_t)(l * B8 + jj) * NELEM;
    int pBase = tp * BM, qBase = tq * BN;

    int tid = threadIdx.x;
    int warp = tid >> 5, lane = tid & 31;
    int wm = (warp >> 2) * 64;              /* warp tile 64x32 */
    int wn = (warp & 3) * 32;
    int qr = lane >> 2;                     /* 0..7 */
    int qc = (lane & 3) * 2;                /* 0,2,4,6 */

    if (tid < BM) {
        int pg = pBase + tid;
        s_ssA[tid] = (pg < PP) ? g_ssf[(l * B8 + ii) * PP + pg] : 0.f;
    } else {
        int q = tid - BM;
        int qg = qBase + q;
        s_ssB[q] = (qg < PP) ? g_ssf[(l * B8 + jj) * PP + qg] : 0.f;
    }

    float c1[4][4][4], c2[4][4][4];
#pragma unroll
    for (int i = 0; i < 4; i++)
#pragma unroll
        for (int j = 0; j < 4; j++)
#pragma unroll
            for (int k = 0; k < 4; k++) { c1[i][j][k] = 0.f; c2[i][j][k] = 0.f; }

    const uint4 z4 = make_uint4(0u, 0u, 0u, 0u);
    const int s0 = tid, s1 = tid + 256;     /* 512 uint4 slots per array */
    const int r0 = s0 >> 2, c80 = (s0 & 3) * 8;
    const int r1 = s1 >> 2, c81 = (s1 & 3) * 8;
    const bool aok0 = (pBase + r0) < PP, aok1 = (pBase + r1) < PP;
    const bool bok0 = (qBase + r0) < PP, bok1 = (qBase + r1) < PP;
    const size_t aoff0 = (size_t)(pBase + r0) * DD;
    const size_t aoff1 = (size_t)(pBase + r1) * DD;
    const size_t boff0 = (size_t)(qBase + r0) * DD;
    const size_t boff1 = (size_t)(qBase + r1) * DD;

    for (int k0 = 0; k0 < DD; k0 += BK) {
        uint4 ah0 = aok0 ? *(const uint4*)(A_h + aoff0 + k0 + c80) : z4;
        uint4 ah1 = aok1 ? *(const uint4*)(A_h + aoff1 + k0 + c81) : z4;
        uint4 al0 = aok0 ? *(const uint4*)(A_l + aoff0 + k0 + c80) : z4;
        uint4 al1 = aok1 ? *(const uint4*)(A_l + aoff1 + k0 + c81) : z4;
        uint4 bh0 = bok0 ? *(const uint4*)(B_h + boff0 + k0 + c80) : z4;
        uint4 bh1 = bok1 ? *(const uint4*)(B_h + boff1 + k0 + c81) : z4;
        uint4 bl0 = bok0 ? *(const uint4*)(B_l + boff0 + k0 + c80) : z4;
        uint4 bl1 = bok1 ? *(const uint4*)(B_l + boff1 + k0 + c81) : z4;
        __syncthreads();
        *(uint4*)&Ah[r0][c80] = ah0;  *(uint4*)&Ah[r1][c81] = ah1;
        *(uint4*)&Al[r0][c80] = al0;  *(uint4*)&Al[r1][c81] = al1;
        *(uint4*)&Bh[r0][c80] = bh0;  *(uint4*)&Bh[r1][c81] = bh1;
        *(uint4*)&Bl[r0][c80] = bl0;  *(uint4*)&Bl[r1][c81] = bl1;
        __syncthreads();

#pragma unroll
        for (int ks = 0; ks < BK; ks += 16) {
            unsigned fah[4][4], fal[4][4], fbh[4][2], fbl[4][2];
#pragma unroll
            for (int mt = 0; mt < 4; mt++) {
                const __half* ba = &Ah[wm + mt * 16 + qr][ks + qc];
                const __half* la = &Al[wm + mt * 16 + qr][ks + qc];
                fah[mt][0] = *(const unsigned*)(ba);
                fah[mt][1] = *(const unsigned*)(ba + 8 * SPAD);
                fah[mt][2] = *(const unsigned*)(ba + 8);
                fah[mt][3] = *(const unsigned*)(ba + 8 * SPAD + 8);
                fal[mt][0] = *(const unsigned*)(la);
                fal[mt][1] = *(const unsigned*)(la + 8 * SPAD);
                fal[mt][2] = *(const unsigned*)(la + 8);
                fal[mt][3] = *(const unsigned*)(la + 8 * SPAD + 8);
            }
#pragma unroll
            for (int nt = 0; nt < 4; nt++) {
                const __half* bb = &Bh[wn + nt * 8 + qr][ks + qc];
                const __half* lb = &Bl[wn + nt * 8 + qr][ks + qc];
                fbh[nt][0] = *(const unsigned*)(bb);
                fbh[nt][1] = *(const unsigned*)(bb + 8);
                fbl[nt][0] = *(const unsigned*)(lb);
                fbl[nt][1] = *(const unsigned*)(lb + 8);
            }
#pragma unroll
            for (int mt = 0; mt < 4; mt++)
#pragma unroll
                for (int nt = 0; nt < 4; nt++) {
                    mma_f16(c1[mt][nt], fah[mt][0], fah[mt][1], fah[mt][2],
                            fah[mt][3], fbh[nt][0], fbh[nt][1]);
                    mma_f16(c2[mt][nt], fah[mt][0], fah[mt][1], fah[mt][2],
                            fah[mt][3], fbl[nt][0], fbl[nt][1]);
                    mma_f16(c2[mt][nt], fal[mt][0], fal[mt][1], fal[mt][2],
                            fal[mt][3], fbh[nt][0], fbh[nt][1]);
                }
        }
        __syncthreads();
    }

    /* dot = c1 + c2/2048; write key matrices (both orientations) */
    size_t dbase = (size_t)(l * NPAIR + pairId) * PP * PP;
#pragma unroll
    for (int mt = 0; mt < 4; mt++) {
#pragma unroll
        for (int nt = 0; nt < 4; nt++) {
#pragma unroll
            for (int k = 0; k < 4; k++) {
                int pl = wm + mt * 16 + qr + ((k >= 2) ? 8 : 0);
                int ql = wn + nt * 8 + qc + (k & 1);
                int pg = pBase + pl, qg = qBase + ql;
                if (pg < PP && qg < PP) {
                    float dot2 = 2.f * fmaf(c2[mt][nt][k], INV_LSCALE,
                                            c1[mt][nt][k]);
                    g_D [dbase + (size_t)pg * PP + qg] = dot2 - s_ssB[ql];
                    g_DT[dbase + (size_t)qg * PP + pg] = dot2 - s_ssA[pl];
                }
            }
        }
    }
}

/* ---- deterministic row scan + fp64 refinement of near-ties --------------- */
__global__ void scan_min() {
    int lz = blockIdx.z;            /* l*2 + dir */
    int l = lz >> 1, dir = lz & 1;
    int pairId = blockIdx.y;
    int warp = threadIdx.x >> 5, lane = threadIdx.x & 31;
    int row = blockIdx.x * 8 + warp;
    if (row >= PP) return;

    int ii = 0, rem = pairId;
    while (rem >= 7 - ii) { rem -= 7 - ii; ii++; }
    int jj = ii + 1 + rem;

    int qimg = dir ? jj : ii;       /* query image     */
    int rimg = dir ? ii : jj;       /* reference image */
    int slot = dir ? ii : (jj - 1);

    const float* M = (dir ? g_DT : g_D)
                   + (size_t)(l * NPAIR + pairId) * PP * PP + (size_t)row * PP;

    /* phase 1: best packed key (tie -> smallest index) */
    unsigned long long best = 0ULL;
    for (int q = lane; q < PP; q += 32) {
        unsigned long long e = packmax(M[q], q);
        if (e > best) best = e;
    }
#pragma unroll
    for (int o = 16; o > 0; o >>= 1) {
        unsigned long long other = __shfl_xor_sync(0xFFFFFFFFu, best, o);
        if (other > best) best = other;
    }
    float bestKey = unpackval(best);

    /* phase 2: flag near-ties */
    unsigned flags[43];
    int total = 0;
    int nk = 0;
    for (int q0 = 0; q0 < PP; q0 += 32) {
        int q = q0 + lane;
        bool f = (q < PP) && (M[q] >= bestKey - DELTA);
        unsigned bal = __ballot_sync(0xFFFFFFFFu, f);
        flags[nk++] = bal;
        total += __popc(bal);
    }

    unsigned long long chosen;
    if (total <= 1) {
        chosen = best;
    } else {
        /* fp64 refinement: exact dot over flagged candidates, q ascending */
        const __half* Xh = g_Xh + (size_t)(l * B8 + qimg) * NELEM
                         + (size_t)row * DD;
        const __half* Xl = g_Xl + (size_t)(l * B8 + qimg) * NELEM
                         + (size_t)row * DD;
        double bkey = -1e300;
        int bq = 0;
        for (int k = 0; k < nk; k++) {
            unsigned bal = flags[k];
            while (bal) {
                int b = __ffs(bal) - 1;
                bal &= bal - 1;
                int q = k * 32 + b;
                const __half* Yh = g_Xh + (size_t)(l * B8 + rimg) * NELEM
                                 + (size_t)q * DD;
                const __half* Yl = g_Xl + (size_t)(l * B8 + rimg) * NELEM
                                 + (size_t)q * DD;
                double s = 0.0;
                for (int e = lane; e < DD; e += 32) {
                    double x = (double)__half2float(Xh[e])
                             + (double)__half2float(Xl[e]) * (double)INV_LSCALE;
                    double y = (double)__half2float(Yh[e])
                             + (double)__half2float(Yl[e]) * (double)INV_LSCALE;
                    s = fma(x, y, s);
                }
#pragma unroll
                for (int o = 16; o > 0; o >>= 1)
                    s += __shfl_xor_sync(0xFFFFFFFFu, s, o);
                double key = 2.0 * s - g_ssd[(l * B8 + rimg) * PP + q];
                if (key > bkey) { bkey = key; bq = q; }
            }
        }
        chosen = packmax((float)bkey, bq);
    }
    if (lane == 0)
        g_best[((size_t)(l * B8 + qimg) * PP + row) * NP + slot] = chosen;
}

/* ---------------- drain: dist, argmin output, per-(r,l) score ------------- */
__global__ void drain(float* __restrict__ out, int rIdx) {
    int idx = blockIdx.x * blockDim.x + threadIdx.x;
    if (idx >= L4 * B8 * PP) return;
    int p  = idx % PP;
    int lb = idx / PP;
    int b = lb % B8, l = lb / B8;

    float q2p = g_ssf[lb * PP + p];
    size_t base = (size_t)idx * NP;
    float m0 = 3e38f, m1 = 3e38f;
#pragma unroll
    for (int s = 0; s < NP; s++) {
        unsigned long long pk = g_best[base + s];
        float key = unpackval(pk);             /* 2*dot - r2_q */
        float dist = sqrtf(fmaxf(0.f, q2p - key));
        int q = (int)(0x7FFFFFFFu - (unsigned int)(pk & 0xFFFFFFFFu));
        out[IDX_OFF +
            ((((size_t)b * L4 + l) * 3 + rIdx) * NP + s) * PP + p] = (float)q;
        if (dist < m0) { m1 = m0; m0 = dist; }
        else if (dist < m1) { m1 = dist; }
    }
    g_scorep[(size_t)(rIdx * L4 + l) * (B8 * PP) + b * PP + p] =
        0.5f * (m0 + m1);
}

/* ---------------- finalize scores ----------------------------------------- */
__global__ void finalize_scores() {
    int idx = blockIdx.x * blockDim.x + threadIdx.x;
    if (idx >= B8 * PP) return;
    float s = 0.f;
    for (int k = 0; k < 12; k++) s += g_scorep[(size_t)k * (B8 * PP) + idx];
    g_scores[idx] = s * (1.0f / 12.0f);
}

__global__ void simg_max() {
    int b = blockIdx.x;
    __shared__ float red[128];
    float m = -3e38f;
    for (int p = threadIdx.x; p < PP; p += 128)
        m = fmaxf(m, g_scores[b * PP + p]);
    red[threadIdx.x] = m;
    __syncthreads();
    for (int o = 64; o > 0; o >>= 1) {
        if (threadIdx.x < o)
            red[threadIdx.x] = fmaxf(red[threadIdx.x], red[threadIdx.x + o]);
        __syncthreads();
    }
    if (threadIdx.x == 0) g_simg[b] = red[0];
}

/* ---------------- bilinear upsample 37x37 -> 518x518 ---------------------- */
__global__ void pixel_kernel(float* __restrict__ out) {
    const int total = B8 * HH * HH;
    int idx = blockIdx.x * blockDim.x + threadIdx.x;
    if (idx >= total) return;
    int w = idx % HH;
    int rest = idx / HH;
    int h = rest % HH;
    int b = rest / HH;

    const float scale = (float)(36.0 / 517.0);
    float cy = (float)h * scale;
    int y0 = (int)cy; if (y0 > 36) y0 = 36;
    int y1 = y0 + 1 < 37 ? y0 + 1 : 36;
    float wy = cy - (float)y0;
    float cx = (float)w * scale;
    int x0 = (int)cx; if (x0 > 36) x0 = 36;
    int x1 = x0 + 1 < 37 ? x0 + 1 : 36;
    float wx = cx - (float)x0;

    const float* S = g_scores + b * PP;
    float v00 = S[y0 * PHW + x0], v01 = S[y0 * PHW + x1];
    float v10 = S[y1 * PHW + x0], v11 = S[y1 * PHW + x1];
    float top = (1.f - wx) * v00 + wx * v01;
    float bot = (1.f - wx) * v10 + wx * v11;
    out[PIXEL_OFF + idx] = (1.f - wy) * top + wy * bot;
}

/* ---------------- RsCIN final scores -------------------------------------- */
__global__ void rscin_kernel(const float* __restrict__ cls,
                             float* __restrict__ out) {
    __shared__ float sd[8][8];
    __shared__ float si[8];
    int t = threadIdx.x;               /* 64 threads */
    int i = t >> 3, j = t & 7;
    float d = 0.f;
    for (int k = 0; k < 768; k++) d += cls[i * 768 + k] * cls[j * 768 + k];
    sd[i][j] = d;
    if (t < 8) si[t] = g_simg[t];
    __syncthreads();

    if (t < 8) {
        int b = t;
        float sim[8];
        float dbb = sd[b][b];
#pragma unroll
        for (int jj = 0; jj < 8; jj++)
            sim[jj] = sd[b][jj] / sqrtf(dbb * sd[jj][jj]);

        bool used[8] = {false, false, false, false, false, false, false, false};
        float wsum = 0.f, acc = 0.f, fin = 0.f;
        for (int kk = 0; kk < 3; kk++) {
            int bi = 0; float bv = -3e38f;
            for (int j2 = 0; j2 < 8; j2++)
                if (!used[j2] && sim[j2] > bv) { bv = sim[j2]; bi = j2; }
            used[bi] = true;
            wsum += bv;
            acc += bv * si[bi];
            fin += acc / wsum;          /* result for k = kk+1 */
        }
        out[b] = fin * (1.0f / 3.0f);
    }
}

/* ---------------- launch -------------------------------------------------- */
extern "C" void kernel_launch(void* const* d_in, const int* in_sizes, int n_in,
                              void* d_out, int out_size) {
    const float* feat = (const float*)d_in[0];
    const float* cls  = (const float*)d_in[1];
    float* out = (float*)d_out;

    ln_stats1<<<dim3(NGROUP, 8), 256>>>(feat);
    ln_stats2<<<1, 32>>>();
    ln_apply<<<4096, 256>>>(feat);

    const int rlist[3] = {1, 3, 5};
    for (int ri = 0; ri < 3; ri++) {
        smooth_norm<<<dim3(PP, NGROUP), 256>>>(rlist[ri]);
        sumsq_d<<<NGROUP * PP, 128>>>();
        gemm_mma<<<dim3(NTILE * NTILE * NPAIR, L4), 256>>>();
        scan_min<<<dim3((PP + 7) / 8, NPAIR, L4 * 2), 256>>>();
        drain<<<(L4 * B8 * PP + 255) / 256, 256>>>(out, ri);
    }

    finalize_scores<<<(B8 * PP + 255) / 256, 256>>>();
    simg_max<<<B8, 128>>>();
    pixel_kernel<<<(B8 * HH * HH + 255) / 256, 256>>>(out);
    rscin_kernel<<<1, 64>>>(cls, out);
}

// round 14
// speedup vs baseline: 2.9751x; 2.9526x over previous
#include <cuda_runtime.h>
#include <cuda_fp16.h>

#define L4 4
#define B8 8
#define PP 1369
#define DD 1024
#define NP 7            /* B-1 */
#define NPAIR 28
#define PHW 37
#define HH 518
#define NGROUP 32       /* L*B */
#define NELEM (PP*DD)
#define TOTAL (NGROUP*NELEM)
#define NTILE 11        /* ceil(1369/128) */
#define LN_EPS 1e-5f
#define LSCALE 2048.0f
#define INV_LSCALE (1.0f/2048.0f)
#define DELTA 2.5e-4f   /* near-tie window on key scale (2*dot) */

#define PIXEL_OFF 8
#define IDX_OFF (8 + B8*HH*HH)

/* ---------------- scratch (static device globals: allocation-free) -------- */
__device__ float g_fn[TOTAL];                       /* layernormed features  */
__device__ __half g_Xh[TOTAL];                      /* split hi (fp16)       */
__device__ __half g_Xl[TOTAL];                      /* split lo*2048 (fp16)  */
__device__ float g_D [(size_t)L4 * NPAIR * PP * PP];   /* row keys [p][q]    */
__device__ float g_DT[(size_t)L4 * NPAIR * PP * PP];   /* col keys [q][p]    */
__device__ double g_ssd[NGROUP * PP];               /* fp64 sumsq quantized  */
__device__ float  g_ssf[NGROUP * PP];
__device__ float g_part[NGROUP * 8 * 2];
__device__ float g_stats[NGROUP * 2];
__device__ unsigned long long g_best[L4 * B8 * PP * NP];
__device__ float g_scorep[12 * B8 * PP];
__device__ float g_scores[B8 * PP];
__device__ float g_simg[B8];

/* ---------------- helpers ------------------------------------------------- */
__device__ __forceinline__ unsigned long long packmax(float v, int q) {
    unsigned int b = __float_as_uint(v);
    b = (b & 0x80000000u) ? ~b : (b | 0x80000000u);   /* monotonic float key */
    return ((unsigned long long)b << 32) |
           (unsigned long long)(0x7FFFFFFFu - (unsigned int)q);
}

__device__ __forceinline__ float unpackval(unsigned long long pk) {
    unsigned int hi = (unsigned int)(pk >> 32);
    unsigned int bits = (hi & 0x80000000u) ? (hi ^ 0x80000000u) : ~hi;
    return __uint_as_float(bits);
}

/* ---------------- LayerNorm ---------------------------------------------- */
__global__ void ln_stats1(const float* __restrict__ x) {
    int g = blockIdx.x, s = blockIdx.y;
    const int chunk = NELEM / 8;
    size_t base = (size_t)g * NELEM + (size_t)s * chunk;
    float sum = 0.f, sq = 0.f;
    for (int i = threadIdx.x; i < chunk; i += blockDim.x) {
        float v = x[base + i];
        sum += v; sq += v * v;
    }
    __shared__ float r1[256], r2[256];
    r1[threadIdx.x] = sum; r2[threadIdx.x] = sq;
    __syncthreads();
    for (int o = 128; o > 0; o >>= 1) {
        if (threadIdx.x < o) {
            r1[threadIdx.x] += r1[threadIdx.x + o];
            r2[threadIdx.x] += r2[threadIdx.x + o];
        }
        __syncthreads();
    }
    if (threadIdx.x == 0) {
        g_part[(g * 8 + s) * 2 + 0] = r1[0];
        g_part[(g * 8 + s) * 2 + 1] = r2[0];
    }
}

__global__ void ln_stats2() {
    int t = threadIdx.x;
    if (t < NGROUP) {
        float sum = 0.f, sq = 0.f;
        for (int s = 0; s < 8; s++) {
            sum += g_part[(t * 8 + s) * 2 + 0];
            sq  += g_part[(t * 8 + s) * 2 + 1];
        }
        float mean = sum / (float)NELEM;
        float var  = sq / (float)NELEM - mean * mean;
        g_stats[t * 2 + 0] = mean;
        g_stats[t * 2 + 1] = 1.0f / sqrtf(var + LN_EPS);
    }
}

__global__ void ln_apply(const float* __restrict__ x) {
    const int n4 = TOTAL / 4;
    const int g4 = NELEM / 4;
    for (int i = blockIdx.x * blockDim.x + threadIdx.x; i < n4;
         i += gridDim.x * blockDim.x) {
        int g = i / g4;
        float mean = g_stats[g * 2 + 0];
        float inv  = g_stats[g * 2 + 1];
        float4 v = ((const float4*)x)[i];
        v.x = (v.x - mean) * inv;
        v.y = (v.y - mean) * inv;
        v.z = (v.z - mean) * inv;
        v.w = (v.w - mean) * inv;
        ((float4*)g_fn)[i] = v;
    }
}

/* --- box smooth + row L2 normalize + scaled fp16 split -------------------- */
__global__ void smooth_norm(int r) {
    int p  = blockIdx.x;
    int lb = blockIdx.y;
    int py = p / PHW, px = p % PHW;
    int pad = r >> 1;
    int t = threadIdx.x;                     /* 256 threads, 4 floats each */
    const float4* src = (const float4*)g_fn + (size_t)lb * (NELEM / 4);

    float4 acc = make_float4(0.f, 0.f, 0.f, 0.f);
    for (int dy = -pad; dy <= pad; dy++) {
        int ny = py + dy;
        if ((unsigned)ny >= PHW) continue;
        for (int dx = -pad; dx <= pad; dx++) {
            int nx = px + dx;
            if ((unsigned)nx >= PHW) continue;
            float4 v = src[(ny * PHW + nx) * (DD / 4) + t];
            acc.x += v.x; acc.y += v.y; acc.z += v.z; acc.w += v.w;
        }
    }
    float inv_rr = 1.0f / (float)(r * r);
    acc.x *= inv_rr; acc.y *= inv_rr; acc.z *= inv_rr; acc.w *= inv_rr;

    float ss = acc.x * acc.x + acc.y * acc.y + acc.z * acc.z + acc.w * acc.w;
    __shared__ float red[256];
    red[t] = ss;
    __syncthreads();
    for (int o = 128; o > 0; o >>= 1) {
        if (t < o) red[t] += red[t + o];
        __syncthreads();
    }
    __shared__ float s_inv;
    if (t == 0) s_inv = 1.0f / sqrtf(red[0]);
    __syncthreads();
    float iv = s_inv;
    float v[4] = {acc.x * iv, acc.y * iv, acc.z * iv, acc.w * iv};

    ushort4 hpack, lpack;
    {
        unsigned short hp[4], lp[4];
#pragma unroll
        for (int e = 0; e < 4; e++) {
            __half h = __float2half_rn(v[e]);
            float hf = __half2float(h);
            __half lq = __float2half_rn((v[e] - hf) * LSCALE);
            hp[e] = __half_as_ushort(h);
            lp[e] = __half_as_ushort(lq);
        }
        hpack = make_ushort4(hp[0], hp[1], hp[2], hp[3]);
        lpack = make_ushort4(lp[0], lp[1], lp[2], lp[3]);
    }
    size_t e4 = ((size_t)lb * NELEM + (size_t)p * DD) / 4 + t;
    ((ushort4*)g_Xh)[e4] = hpack;
    ((ushort4*)g_Xl)[e4] = lpack;
}

/* --------- fp64 sumsq of quantized patch vectors (deterministic) ---------- */
__global__ void sumsq_d() {
    int pidx = blockIdx.x;                  /* lb*PP + p */
    const __half* Xh = g_Xh + (size_t)pidx * DD;
    const __half* Xl = g_Xl + (size_t)pidx * DD;
    int t = threadIdx.x;                    /* 128 threads */
    double s = 0.0;
    for (int e = t; e < DD; e += 128) {
        double x = (double)__half2float(Xh[e])
                 + (double)__half2float(Xl[e]) * (double)INV_LSCALE;
        s = fma(x, x, s);
    }
    __shared__ double red[128];
    red[t] = s;
    __syncthreads();
    for (int o = 64; o > 0; o >>= 1) {
        if (t < o) red[t] += red[t + o];
        __syncthreads();
    }
    if (t == 0) { g_ssd[pidx] = red[0]; g_ssf[pidx] = (float)red[0]; }
}

/* -------- Gram GEMM (fp16 hi only, mma.sync) -> key matrices D, DT -------- */
#define BM 128
#define BN 128
#define BK 32
#define SPAD (BK + 8)           /* 40 halves stride: conflict-free */

__device__ __forceinline__ void mma_f16(float c[4], unsigned a0, unsigned a1,
                                        unsigned a2, unsigned a3,
                                        unsigned b0, unsigned b1) {
    asm volatile(
        "mma.sync.aligned.m16n8k16.row.col.f32.f16.f16.f32 "
        "{%0,%1,%2,%3}, {%4,%5,%6,%7}, {%8,%9}, {%0,%1,%2,%3};\n"
        : "+f"(c[0]), "+f"(c[1]), "+f"(c[2]), "+f"(c[3])
        : "r"(a0), "r"(a1), "r"(a2), "r"(a3), "r"(b0), "r"(b1));
}

__global__ __launch_bounds__(256, 2) void gemm_mma() {
    __shared__ __align__(16) __half Ah[BM][SPAD];
    __shared__ __align__(16) __half Bh[BN][SPAD];
    __shared__ float s_ssA[BM];          /* q2 of A-rows  */
    __shared__ float s_ssB[BN];          /* r2 of B-rows  */

    int l = blockIdx.y;
    int t = blockIdx.x;
    int tileId = t % (NTILE * NTILE);
    int pairId = t / (NTILE * NTILE);
    int tp = tileId / NTILE, tq = tileId % NTILE;

    int ii = 0, rem = pairId;
    while (rem >= 7 - ii) { rem -= 7 - ii; ii++; }
    int jj = ii + 1 + rem;                  /* pair (ii < jj) */

    const __half* A_h = g_Xh + (size_t)(l * B8 + ii) * NELEM;
    const __half* B_h = g_Xh + (size_t)(l * B8 + jj) * NELEM;
    int pBase = tp * BM, qBase = tq * BN;

    int tid = threadIdx.x;
    int warp = tid >> 5, lane = tid & 31;
    int wm = (warp >> 2) * 64;              /* warp tile 64x32 */
    int wn = (warp & 3) * 32;
    int qr = lane >> 2;                     /* 0..7 */
    int qc = (lane & 3) * 2;                /* 0,2,4,6 */

    if (tid < BM) {
        int pg = pBase + tid;
        s_ssA[tid] = (pg < PP) ? g_ssf[(l * B8 + ii) * PP + pg] : 0.f;
    } else {
        int q = tid - BM;
        int qg = qBase + q;
        s_ssB[q] = (qg < PP) ? g_ssf[(l * B8 + jj) * PP + qg] : 0.f;
    }

    float c1[4][4][4];
#pragma unroll
    for (int i = 0; i < 4; i++)
#pragma unroll
        for (int j = 0; j < 4; j++)
#pragma unroll
            for (int k = 0; k < 4; k++) c1[i][j][k] = 0.f;

    const uint4 z4 = make_uint4(0u, 0u, 0u, 0u);
    const int s0 = tid, s1 = tid + 256;     /* 512 uint4 slots per array */
    const int r0 = s0 >> 2, c80 = (s0 & 3) * 8;
    const int r1 = s1 >> 2, c81 = (s1 & 3) * 8;
    const bool aok0 = (pBase + r0) < PP, aok1 = (pBase + r1) < PP;
    const bool bok0 = (qBase + r0) < PP, bok1 = (qBase + r1) < PP;
    const size_t aoff0 = (size_t)(pBase + r0) * DD;
    const size_t aoff1 = (size_t)(pBase + r1) * DD;
    const size_t boff0 = (size_t)(qBase + r0) * DD;
    const size_t boff1 = (size_t)(qBase + r1) * DD;

    for (int k0 = 0; k0 < DD; k0 += BK) {
        uint4 ah0 = aok0 ? *(const uint4*)(A_h + aoff0 + k0 + c80) : z4;
        uint4 ah1 = aok1 ? *(const uint4*)(A_h + aoff1 + k0 + c81) : z4;
        uint4 bh0 = bok0 ? *(const uint4*)(B_h + boff0 + k0 + c80) : z4;
        uint4 bh1 = bok1 ? *(const uint4*)(B_h + boff1 + k0 + c81) : z4;
        __syncthreads();
        *(uint4*)&Ah[r0][c80] = ah0;  *(uint4*)&Ah[r1][c81] = ah1;
        *(uint4*)&Bh[r0][c80] = bh0;  *(uint4*)&Bh[r1][c81] = bh1;
        __syncthreads();

#pragma unroll
        for (int ks = 0; ks < BK; ks += 16) {
            unsigned fah[4][4], fbh[4][2];
#pragma unroll
            for (int mt = 0; mt < 4; mt++) {
                const __half* ba = &Ah[wm + mt * 16 + qr][ks + qc];
                fah[mt][0] = *(const unsigned*)(ba);
                fah[mt][1] = *(const unsigned*)(ba + 8 * SPAD);
                fah[mt][2] = *(const unsigned*)(ba + 8);
                fah[mt][3] = *(const unsigned*)(ba + 8 * SPAD + 8);
            }
#pragma unroll
            for (int nt = 0; nt < 4; nt++) {
                const __half* bb = &Bh[wn + nt * 8 + qr][ks + qc];
                fbh[nt][0] = *(const unsigned*)(bb);
                fbh[nt][1] = *(const unsigned*)(bb + 8);
            }
#pragma unroll
            for (int mt = 0; mt < 4; mt++)
#pragma unroll
                for (int nt = 0; nt < 4; nt++)
                    mma_f16(c1[mt][nt], fah[mt][0], fah[mt][1], fah[mt][2],
                            fah[mt][3], fbh[nt][0], fbh[nt][1]);
        }
        __syncthreads();
    }

    /* dot = c1 (hi*hi); write key matrices (both orientations) */
    size_t dbase = (size_t)(l * NPAIR + pairId) * PP * PP;
#pragma unroll
    for (int mt = 0; mt < 4; mt++) {
#pragma unroll
        for (int nt = 0; nt < 4; nt++) {
#pragma unroll
            for (int k = 0; k < 4; k++) {
                int pl = wm + mt * 16 + qr + ((k >= 2) ? 8 : 0);
                int ql = wn + nt * 8 + qc + (k & 1);
                int pg = pBase + pl, qg = qBase + ql;
                if (pg < PP && qg < PP) {
                    float dot2 = 2.f * c1[mt][nt][k];
                    g_D [dbase + (size_t)pg * PP + qg] = dot2 - s_ssB[ql];
                    g_DT[dbase + (size_t)qg * PP + pg] = dot2 - s_ssA[pl];
                }
            }
        }
    }
}

/* ---- deterministic row scan + fp64 refinement of near-ties --------------- */
__global__ void scan_min() {
    int lz = blockIdx.z;            /* l*2 + dir */
    int l = lz >> 1, dir = lz & 1;
    int pairId = blockIdx.y;
    int warp = threadIdx.x >> 5, lane = threadIdx.x & 31;
    int row = blockIdx.x * 8 + warp;
    if (row >= PP) return;

    int ii = 0, rem = pairId;
    while (rem >= 7 - ii) { rem -= 7 - ii; ii++; }
    int jj = ii + 1 + rem;

    int qimg = dir ? jj : ii;       /* query image     */
    int rimg = dir ? ii : jj;       /* reference image */
    int slot = dir ? ii : (jj - 1);

    const float* M = (dir ? g_DT : g_D)
                   + (size_t)(l * NPAIR + pairId) * PP * PP + (size_t)row * PP;

    /* phase 1: best packed key (tie -> smallest index) */
    unsigned long long best = 0ULL;
    for (int q = lane; q < PP; q += 32) {
        unsigned long long e = packmax(M[q], q);
        if (e > best) best = e;
    }
#pragma unroll
    for (int o = 16; o > 0; o >>= 1) {
        unsigned long long other = __shfl_xor_sync(0xFFFFFFFFu, best, o);
        if (other > best) best = other;
    }
    float bestKey = unpackval(best);

    /* phase 2: flag near-ties */
    unsigned flags[43];
    int total = 0;
    int nk = 0;
    for (int q0 = 0; q0 < PP; q0 += 32) {
        int q = q0 + lane;
        bool f = (q < PP) && (M[q] >= bestKey - DELTA);
        unsigned bal = __ballot_sync(0xFFFFFFFFu, f);
        flags[nk++] = bal;
        total += __popc(bal);
    }

    unsigned long long chosen;
    if (total <= 1) {
        chosen = best;
    } else {
        /* fp64 refinement: exact dot over flagged candidates, q ascending */
        const __half* Xh = g_Xh + (size_t)(l * B8 + qimg) * NELEM
                         + (size_t)row * DD;
        const __half* Xl = g_Xl + (size_t)(l * B8 + qimg) * NELEM
                         + (size_t)row * DD;
        double bkey = -1e300;
        int bq = 0;
        for (int k = 0; k < nk; k++) {
            unsigned bal = flags[k];
            while (bal) {
                int b = __ffs(bal) - 1;
                bal &= bal - 1;
                int q = k * 32 + b;
                const __half* Yh = g_Xh + (size_t)(l * B8 + rimg) * NELEM
                                 + (size_t)q * DD;
                const __half* Yl = g_Xl + (size_t)(l * B8 + rimg) * NELEM
                                 + (size_t)q * DD;
                double s = 0.0;
                for (int e = lane; e < DD; e += 32) {
                    double x = (double)__half2float(Xh[e])
                             + (double)__half2float(Xl[e]) * (double)INV_LSCALE;
                    double y = (double)__half2float(Yh[e])
                             + (double)__half2float(Yl[e]) * (double)INV_LSCALE;
                    s = fma(x, y, s);
                }
#pragma unroll
                for (int o = 16; o > 0; o >>= 1)
                    s += __shfl_xor_sync(0xFFFFFFFFu, s, o);
                double key = 2.0 * s - g_ssd[(l * B8 + rimg) * PP + q];
                if (key > bkey) { bkey = key; bq = q; }
            }
        }
        chosen = packmax((float)bkey, bq);
    }
    if (lane == 0)
        g_best[((size_t)(l * B8 + qimg) * PP + row) * NP + slot] = chosen;
}

/* ---------------- drain: dist, argmin output, per-(r,l) score ------------- */
__global__ void drain(float* __restrict__ out, int rIdx) {
    int idx = blockIdx.x * blockDim.x + threadIdx.x;
    if (idx >= L4 * B8 * PP) return;
    int p  = idx % PP;
    int lb = idx / PP;
    int b = lb % B8, l = lb / B8;

    float q2p = g_ssf[lb * PP + p];
    size_t base = (size_t)idx * NP;
    float m0 = 3e38f, m1 = 3e38f;
#pragma unroll
    for (int s = 0; s < NP; s++) {
        unsigned long long pk = g_best[base + s];
        float key = unpackval(pk);             /* 2*dot - r2_q */
        float dist = sqrtf(fmaxf(0.f, q2p - key));
        int q = (int)(0x7FFFFFFFu - (unsigned int)(pk & 0xFFFFFFFFu));
        out[IDX_OFF +
            ((((size_t)b * L4 + l) * 3 + rIdx) * NP + s) * PP + p] = (float)q;
        if (dist < m0) { m1 = m0; m0 = dist; }
        else if (dist < m1) { m1 = dist; }
    }
    g_scorep[(size_t)(rIdx * L4 + l) * (B8 * PP) + b * PP + p] =
        0.5f * (m0 + m1);
}

/* ---------------- finalize scores ----------------------------------------- */
__global__ void finalize_scores() {
    int idx = blockIdx.x * blockDim.x + threadIdx.x;
    if (idx >= B8 * PP) return;
    float s = 0.f;
    for (int k = 0; k < 12; k++) s += g_scorep[(size_t)k * (B8 * PP) + idx];
    g_scores[idx] = s * (1.0f / 12.0f);
}

__global__ void simg_max() {
    int b = blockIdx.x;
    __shared__ float red[128];
    float m = -3e38f;
    for (int p = threadIdx.x; p < PP; p += 128)
        m = fmaxf(m, g_scores[b * PP + p]);
    red[threadIdx.x] = m;
    __syncthreads();
    for (int o = 64; o > 0; o >>= 1) {
        if (threadIdx.x < o)
            red[threadIdx.x] = fmaxf(red[threadIdx.x], red[threadIdx.x + o]);
        __syncthreads();
    }
    if (threadIdx.x == 0) g_simg[b] = red[0];
}

/* ---------------- bilinear upsample 37x37 -> 518x518 ---------------------- */
__global__ void pixel_kernel(float* __restrict__ out) {
    const int total = B8 * HH * HH;
    int idx = blockIdx.x * blockDim.x + threadIdx.x;
    if (idx >= total) return;
    int w = idx % HH;
    int rest = idx / HH;
    int h = rest % HH;
    int b = rest / HH;

    const float scale = (float)(36.0 / 517.0);
    float cy = (float)h * scale;
    int y0 = (int)cy; if (y0 > 36) y0 = 36;
    int y1 = y0 + 1 < 37 ? y0 + 1 : 36;
    float wy = cy - (float)y0;
    float cx = (float)w * scale;
    int x0 = (int)cx; if (x0 > 36) x0 = 36;
    int x1 = x0 + 1 < 37 ? x0 + 1 : 36;
    float wx = cx - (float)x0;

    const float* S = g_scores + b * PP;
    float v00 = S[y0 * PHW + x0], v01 = S[y0 * PHW + x1];
    float v10 = S[y1 * PHW + x0], v11 = S[y1 * PHW + x1];
    float top = (1.f - wx) * v00 + wx * v01;
    float bot = (1.f - wx) * v10 + wx * v11;
    out[PIXEL_OFF + idx] = (1.f - wy) * top + wy * bot;
}

/* ---------------- RsCIN final scores -------------------------------------- */
__global__ void rscin_kernel(const float* __restrict__ cls,
                             float* __restrict__ out) {
    __shared__ float sd[8][8];
    __shared__ float si[8];
    int t = threadIdx.x;               /* 64 threads */
    int i = t >> 3, j = t & 7;
    float d = 0.f;
    for (int k = 0; k < 768; k++) d += cls[i * 768 + k] * cls[j * 768 + k];
    sd[i][j] = d;
    if (t < 8) si[t] = g_simg[t];
    __syncthreads();

    if (t < 8) {
        int b = t;
        float sim[8];
        float dbb = sd[b][b];
#pragma unroll
        for (int jj = 0; jj < 8; jj++)
            sim[jj] = sd[b][jj] / sqrtf(dbb * sd[jj][jj]);

        bool used[8] = {false, false, false, false, false, false, false, false};
        float wsum = 0.f, acc = 0.f, fin = 0.f;
        for (int kk = 0; kk < 3; kk++) {
            int bi = 0; float bv = -3e38f;
            for (int j2 = 0; j2 < 8; j2++)
                if (!used[j2] && sim[j2] > bv) { bv = sim[j2]; bi = j2; }
            used[bi] = true;
            wsum += bv;
            acc += bv * si[bi];
            fin += acc / wsum;          /* result for k = kk+1 */
        }
        out[b] = fin * (1.0f / 3.0f);
    }
}

/* ---------------- launch -------------------------------------------------- */
extern "C" void kernel_launch(void* const* d_in, const int* in_sizes, int n_in,
                              void* d_out, int out_size) {
    const float* feat = (const float*)d_in[0];
    const float* cls  = (const float*)d_in[1];
    float* out = (float*)d_out;

    ln_stats1<<<dim3(NGROUP, 8), 256>>>(feat);
    ln_stats2<<<1, 32>>>();
    ln_apply<<<4096, 256>>>(feat);

    const int rlist[3] = {1, 3, 5};
    for (int ri = 0; ri < 3; ri++) {
        smooth_norm<<<dim3(PP, NGROUP), 256>>>(rlist[ri]);
        sumsq_d<<<NGROUP * PP, 128>>>();
        gemm_mma<<<dim3(NTILE * NTILE * NPAIR, L4), 256>>>();
        scan_min<<<dim3((PP + 7) / 8, NPAIR, L4 * 2), 256>>>();
        drain<<<(L4 * B8 * PP + 255) / 256, 256>>>(out, ri);
    }

    finalize_scores<<<(B8 * PP + 255) / 256, 256>>>();
    simg_max<<<B8, 128>>>();
    pixel_kernel<<<(B8 * HH * HH + 255) / 256, 256>>>(out);
    rscin_kernel<<<1, 64>>>(cls, out);
}